// round 2
// baseline (speedup 1.0000x reference)
#include <cuda_runtime.h>
#include <math.h>
#include <stdint.h>

// ---------------- problem constants ----------------
#define N_ROWS   8192
#define DIM      1024
#define NCLS     50257
#define SHORT    4000
#define CUT1     20000
#define HEADC    4002          // 4000 shortlist + 2 tail-cluster logits
#define SEG1C    16000         // [4000,20000)
#define SEG2C    30257         // [20000,50257)

// ---------------- GEMM tiling ----------------
#define BM 128
#define BN 128
#define BK 16

#define HT   32                // ceil(4002/128)
#define S1T  125               // 16000/128
#define S2T  237               // ceil(30257/128)

// ---------------- scratch (static device memory; no allocs) ----------------
__device__ float2 g_headPart[(size_t)N_ROWS * HT];
__device__ float2 g_seg1Part[(size_t)N_ROWS * S1T];
__device__ float2 g_seg2Part[(size_t)N_ROWS * S2T];
__device__ int    g_list1[N_ROWS];
__device__ int    g_list2[N_ROWS];
__device__ int    g_cnt[2];

// ---------------- kernel 0: reset counters ----------------
__global__ void reset_kernel() {
    g_cnt[0] = 0;
    g_cnt[1] = 0;
}

// ---------------- kernel 1: classify rows into tail clusters ----------------
__global__ void classify_kernel(const int* __restrict__ target) {
    int r = blockIdx.x * blockDim.x + threadIdx.x;
    if (r >= N_ROWS) return;
    int t = target[r];
    if (t >= SHORT) {
        if (t < CUT1) {
            int p = atomicAdd(&g_cnt[0], 1);
            g_list1[p] = r;
        } else {
            int p = atomicAdd(&g_cnt[1], 1);
            g_list2[p] = r;
        }
    }
}

// ---------------- kernel 2: tiled GEMM + per-tile (max,sumexp) ----------------
// SEG = 0: head (shortlist + tail vectors), all rows
// SEG = 1: weight[4000:20000), compacted cluster-1 rows
// SEG = 2: weight[20000:50257), compacted cluster-2 rows
template <int SEG>
__global__ __launch_bounds__(256, 2)
void gemm_lse_kernel(const float* __restrict__ input,
                     const float* __restrict__ weight,
                     const float* __restrict__ bias,
                     const float* __restrict__ tailv,
                     const float* __restrict__ tailb)
{
    const int colTile = blockIdx.x;
    const int rowTile = blockIdx.y;

    int count;
    const int* rlist;
    float2* part;
    int tiles;
    if (SEG == 0)      { count = N_ROWS;   rlist = nullptr;  part = g_headPart; tiles = HT;  }
    else if (SEG == 1) { count = g_cnt[0]; rlist = g_list1;  part = g_seg1Part; tiles = S1T; }
    else               { count = g_cnt[1]; rlist = g_list2;  part = g_seg2Part; tiles = S2T; }

    if (rowTile * BM >= count) return;

    const int tid = threadIdx.x;
    const int tx  = tid & 15;
    const int ty  = tid >> 4;

    __shared__ float As[BK][BM + 4];
    __shared__ float Bs[BK][BN + 4];
    __shared__ int   sRow[BM];
    __shared__ const float* sBp[BN];
    __shared__ float sBias[BN];

    if (tid < BM) {
        // row setup
        int gr = rowTile * BM + tid;
        int orig = -1;
        if (gr < count) orig = (SEG == 0) ? gr : rlist[gr];
        sRow[tid] = orig;

        // column setup (segment-local column index)
        int sc = colTile * BN + tid;
        const float* bp = nullptr;
        float bv = -INFINITY;
        if (SEG == 0) {
            if (sc < SHORT)      { bp = weight + (size_t)sc * DIM;            bv = bias[sc]; }
            else if (sc < HEADC) { bp = tailv + (size_t)(sc - SHORT) * DIM;   bv = tailb[sc - SHORT]; }
        } else if (SEG == 1) {
            if (sc < SEG1C)      { bp = weight + (size_t)(SHORT + sc) * DIM;  bv = bias[SHORT + sc]; }
        } else {
            if (sc < SEG2C)      { bp = weight + (size_t)(CUT1 + sc) * DIM;   bv = bias[CUT1 + sc]; }
        }
        sBp[tid]   = bp;
        sBias[tid] = bv;
    }
    __syncthreads();

    float acc[8][8];
#pragma unroll
    for (int i = 0; i < 8; i++)
#pragma unroll
        for (int j = 0; j < 8; j++) acc[i][j] = 0.0f;

    for (int k0 = 0; k0 < DIM; k0 += BK) {
        // cooperative loads: 128 rows x 16 k for both A and B
#pragma unroll
        for (int it = 0; it < 2; it++) {
            int li = tid + it * 256;
            int m  = li >> 2;
            int kq = (li & 3) * 4;

            int orig = sRow[m];
            float4 va = make_float4(0.f, 0.f, 0.f, 0.f);
            if (orig >= 0)
                va = *(const float4*)(input + (size_t)orig * DIM + k0 + kq);
            As[kq + 0][m] = va.x; As[kq + 1][m] = va.y;
            As[kq + 2][m] = va.z; As[kq + 3][m] = va.w;

            const float* bp = sBp[m];
            float4 vb = make_float4(0.f, 0.f, 0.f, 0.f);
            if (bp)
                vb = *(const float4*)(bp + k0 + kq);
            Bs[kq + 0][m] = vb.x; Bs[kq + 1][m] = vb.y;
            Bs[kq + 2][m] = vb.z; Bs[kq + 3][m] = vb.w;
        }
        __syncthreads();

#pragma unroll
        for (int k = 0; k < BK; k++) {
            float4 a0 = *(const float4*)&As[k][ty * 8];
            float4 a1 = *(const float4*)&As[k][ty * 8 + 4];
            float4 b0 = *(const float4*)&Bs[k][tx * 8];
            float4 b1 = *(const float4*)&Bs[k][tx * 8 + 4];
            float a[8] = {a0.x, a0.y, a0.z, a0.w, a1.x, a1.y, a1.z, a1.w};
            float b[8] = {b0.x, b0.y, b0.z, b0.w, b1.x, b1.y, b1.z, b1.w};
#pragma unroll
            for (int i = 0; i < 8; i++)
#pragma unroll
                for (int j = 0; j < 8; j++)
                    acc[i][j] += a[i] * b[j];
        }
        __syncthreads();
    }

    // epilogue: per-row (max, sumexp) over this 128-col tile
    float bj[8];
#pragma unroll
    for (int j = 0; j < 8; j++) bj[j] = sBias[tx * 8 + j];

#pragma unroll
    for (int i = 0; i < 8; i++) {
        int m = ty * 8 + i;
        int orig = sRow[m];
        float t[8];
        float mx = -INFINITY;
#pragma unroll
        for (int j = 0; j < 8; j++) {
            t[j] = acc[i][j] + bj[j];     // invalid cols: bias = -inf -> t = -inf
            mx = fmaxf(mx, t[j]);
        }
#pragma unroll
        for (int off = 8; off; off >>= 1)
            mx = fmaxf(mx, __shfl_xor_sync(0xffffffffu, mx, off));
        float s = 0.f;
#pragma unroll
        for (int j = 0; j < 8; j++)
            s += expf(t[j] - mx);         // exp(-inf - mx) = 0
#pragma unroll
        for (int off = 8; off; off >>= 1)
            s += __shfl_xor_sync(0xffffffffu, s, off);
        if (tx == 0 && orig >= 0)
            part[(size_t)orig * tiles + colTile] = make_float2(mx, s);
    }
}

// ---------------- kernel 3: combine (1 warp per row) ----------------
__global__ void combine_kernel(const float* __restrict__ input,
                               const int*   __restrict__ target,
                               const float* __restrict__ weight,
                               const float* __restrict__ bias,
                               const float* __restrict__ tailv,
                               const float* __restrict__ tailb,
                               float* __restrict__ out)
{
    int gw   = (blockIdx.x * blockDim.x + threadIdx.x) >> 5;
    int lane = threadIdx.x & 31;
    if (gw >= N_ROWS) return;
    const int r = gw;

    const int t = target[r];
    const int cid = (t < SHORT) ? 0 : ((t < CUT1) ? 1 : 2);

    // ---- head LSE: exactly HT=32 tiles, one per lane ----
    float2 hp = g_headPart[(size_t)r * HT + lane];
    float m = hp.x, s = hp.y;
#pragma unroll
    for (int off = 16; off; off >>= 1) {
        float m2 = __shfl_xor_sync(0xffffffffu, m, off);
        float s2 = __shfl_xor_sync(0xffffffffu, s, off);
        float M  = fmaxf(m, m2);
        s = s * expf(m - M) + s2 * expf(m2 - M);
        m = M;
    }
    float lseH = m + logf(s);

    // ---- gathered head logit ----
    const float* v; float bb;
    if (cid == 0) { v = weight + (size_t)t * DIM;          bb = bias[t]; }
    else          { v = tailv + (size_t)(cid - 1) * DIM;   bb = tailb[cid - 1]; }
    const float4* xr = (const float4*)(input + (size_t)r * DIM);
    const float4* vv = (const float4*)v;
    float d = 0.f;
#pragma unroll
    for (int i = lane; i < DIM / 4; i += 32) {
        float4 a = xr[i], b = vv[i];
        d += a.x * b.x + a.y * b.y + a.z * b.z + a.w * b.w;
    }
#pragma unroll
    for (int off = 16; off; off >>= 1)
        d += __shfl_xor_sync(0xffffffffu, d, off);
    float res = (d + bb) - lseH;

    if (cid > 0) {
        // target logit against full table
        const float4* wv = (const float4*)(weight + (size_t)t * DIM);
        float d2 = 0.f;
#pragma unroll
        for (int i = lane; i < DIM / 4; i += 32) {
            float4 a = xr[i], b = wv[i];
            d2 += a.x * b.x + a.y * b.y + a.z * b.z + a.w * b.w;
        }
#pragma unroll
        for (int off = 16; off; off >>= 1)
            d2 += __shfl_xor_sync(0xffffffffu, d2, off);
        float tl = d2 + bias[t];

        // cluster LSE
        const float2* part = (cid == 1) ? (g_seg1Part + (size_t)r * S1T)
                                        : (g_seg2Part + (size_t)r * S2T);
        const int T = (cid == 1) ? S1T : S2T;
        float mm = -INFINITY, ss = 0.f;
        for (int i = lane; i < T; i += 32) {
            float2 q = part[i];
            float M = fmaxf(mm, q.x);
            ss = ss * expf(mm - M) + q.y * expf(q.x - M);
            mm = M;
        }
#pragma unroll
        for (int off = 16; off; off >>= 1) {
            float m2 = __shfl_xor_sync(0xffffffffu, mm, off);
            float s2 = __shfl_xor_sync(0xffffffffu, ss, off);
            float M  = fmaxf(mm, m2);
            if (M == -INFINITY) { mm = M; ss = 0.f; }
            else {
                ss = ss * expf(mm - M) + s2 * expf(m2 - M);
                mm = M;
            }
        }
        float lseS = mm + logf(ss);
        res += tl - lseS;
    }

    if (lane == 0) out[r] = res;
}

// ---------------- kernel 4: deterministic loss reduction ----------------
__global__ void loss_kernel(const float* __restrict__ out_vals,
                            float* __restrict__ loss_out)
{
    __shared__ float red[1024];
    int tid = threadIdx.x;
    float s = 0.f;
    for (int i = tid; i < N_ROWS; i += 1024)
        s += out_vals[i];
    red[tid] = s;
    __syncthreads();
    for (int stride = 512; stride > 0; stride >>= 1) {
        if (tid < stride) red[tid] += red[tid + stride];
        __syncthreads();
    }
    if (tid == 0)
        *loss_out = -red[0] / (float)N_ROWS;
}

// ---------------- launch ----------------
extern "C" void kernel_launch(void* const* d_in, const int* in_sizes, int n_in,
                              void* d_out, int out_size)
{
    const float* input  = (const float*)d_in[0];
    const int*   target = (const int*)  d_in[1];
    const float* weight = (const float*)d_in[2];
    const float* bias   = (const float*)d_in[3];
    const float* tailv  = (const float*)d_in[4];
    const float* tailb  = (const float*)d_in[5];
    float* out = (float*)d_out;

    reset_kernel<<<1, 1>>>();
    classify_kernel<<<N_ROWS / 256, 256>>>(target);

    gemm_lse_kernel<0><<<dim3(HT,  N_ROWS / BM), 256>>>(input, weight, bias, tailv, tailb);
    gemm_lse_kernel<1><<<dim3(S1T, N_ROWS / BM), 256>>>(input, weight, bias, tailv, tailb);
    gemm_lse_kernel<2><<<dim3(S2T, N_ROWS / BM), 256>>>(input, weight, bias, tailv, tailb);

    combine_kernel<<<(N_ROWS * 32) / 256, 256>>>(input, target, weight, bias,
                                                 tailv, tailb, out);

    if (out_size > N_ROWS)
        loss_kernel<<<1, 1024>>>(out, out + N_ROWS);
}

// round 5
// speedup vs baseline: 3.9216x; 3.9216x over previous
#include <cuda_runtime.h>
#include <math.h>
#include <stdint.h>

// ---------------- problem constants ----------------
#define N_ROWS   8192
#define DIM      1024
#define SHORT    4000
#define CUT1     20000
#define HEADC    4002
#define SEG1C    16000
#define SEG2C    30257

// ---------------- GEMM tiling ----------------
#define BM 128
#define BN 128
#define BK 16
#define NSTAGE 3
#define NCHUNK (DIM / BK)      // 64

#define HT   32                // ceil(4002/128)
#define S1T  125
#define S2T  237               // ceil(30257/128)

// smem layout: padded rows (16 data + 4 pad floats) -> conflict-free LDS
#define ROWSTRIDE 20
#define TILE_BYTES (128 * ROWSTRIDE * 4)     // 10240
#define STAGE_BYTES (2 * TILE_BYTES)         // 20480 (A then B)
#define META_OFF (NSTAGE * STAGE_BYTES)      // 61440
#define SBIAS_OFF (META_OFF)                 // 512 B
#define SAP_OFF   (META_OFF + 512)           // 1024 B
#define SBP_OFF   (META_OFF + 1536)          // 1024 B
#define SROW_OFF  (META_OFF + 2560)          // 512 B
#define SRED_OFF  (META_OFF + 3072)          // 2048 B (256 float2)  <-- was 1024: OOB bug
#define SMEM_TOTAL (META_OFF + 5120)         // 66560

// ---------------- scratch ----------------
__device__ float2 g_headPart[(size_t)N_ROWS * HT];
__device__ float2 g_seg1Part[(size_t)N_ROWS * S1T];
__device__ float2 g_seg2Part[(size_t)N_ROWS * S2T];
__device__ int    g_list1[N_ROWS];
__device__ int    g_list2[N_ROWS];
__device__ int    g_cnt[2];

// ---------------- helpers ----------------
__device__ __forceinline__ uint32_t smem_u32(const void* p) {
    uint32_t a;
    asm("{ .reg .u64 t; cvta.to.shared.u64 t, %1; cvt.u32.u64 %0, t; }" : "=r"(a) : "l"(p));
    return a;
}
__device__ __forceinline__ void cp_async16(uint32_t dst, const void* src, uint32_t szbytes) {
    asm volatile("cp.async.cg.shared.global [%0], [%1], 16, %2;\n"
                 :: "r"(dst), "l"(src), "r"(szbytes));
}
__device__ __forceinline__ void cp_commit() { asm volatile("cp.async.commit_group;"); }
__device__ __forceinline__ void cp_wait1()  { asm volatile("cp.async.wait_group 1;"); }
__device__ __forceinline__ void cp_wait0()  { asm volatile("cp.async.wait_group 0;"); }

__device__ __forceinline__ void mma_tf32(float* d, const uint32_t* a, uint32_t b0, uint32_t b1) {
    asm volatile(
        "mma.sync.aligned.m16n8k8.row.col.f32.tf32.tf32.f32 "
        "{%0,%1,%2,%3}, {%4,%5,%6,%7}, {%8,%9}, {%0,%1,%2,%3};\n"
        : "+f"(d[0]), "+f"(d[1]), "+f"(d[2]), "+f"(d[3])
        : "r"(a[0]), "r"(a[1]), "r"(a[2]), "r"(a[3]), "r"(b0), "r"(b1));
}

__device__ __forceinline__ void lse_merge(float& m, float& s, float m2, float s2) {
    float M = fmaxf(m, m2);
    if (M == -INFINITY) { m = M; s = 0.f; return; }
    s = s * expf(m - M) + s2 * expf(m2 - M);
    m = M;
}

// ---------------- small kernels ----------------
__global__ void reset_kernel() { g_cnt[0] = 0; g_cnt[1] = 0; }

__global__ void classify_kernel(const int* __restrict__ target) {
    int r = blockIdx.x * blockDim.x + threadIdx.x;
    if (r >= N_ROWS) return;
    int t = target[r];
    if (t >= SHORT) {
        if (t < CUT1) g_list1[atomicAdd(&g_cnt[0], 1)] = r;
        else          g_list2[atomicAdd(&g_cnt[1], 1)] = r;
    }
}

// ---------------- tensor-core (mma.sync tf32) GEMM + LSE partials ----------------
template <int SEG>
__global__ __launch_bounds__(256)
void gemm_lse_tc(const float* __restrict__ input,
                 const float* __restrict__ weight,
                 const float* __restrict__ bias,
                 const float* __restrict__ tailv,
                 const float* __restrict__ tailb)
{
    const int rowTile = blockIdx.x;
    const int colTile = blockIdx.y;

    int count; const int* rlist; float2* part; int tiles;
    if (SEG == 0)      { count = N_ROWS;   rlist = nullptr; part = g_headPart; tiles = HT;  }
    else if (SEG == 1) { count = g_cnt[0]; rlist = g_list1; part = g_seg1Part; tiles = S1T; }
    else               { count = g_cnt[1]; rlist = g_list2; part = g_seg2Part; tiles = S2T; }
    if (rowTile * BM >= count) return;

    extern __shared__ char smem[];
    const uint32_t sb = smem_u32(smem);
    const int tid  = threadIdx.x;
    const int lane = tid & 31;
    const int wid  = tid >> 5;
    const int warpM = wid >> 1;          // 0..3 -> 32-row band
    const int warpN = wid & 1;           // 0..1 -> 64-col half
    const int g = lane >> 2;             // group id 0..7
    const int t = lane & 3;              // thread-in-group

    float*        sBias = (float*)(smem + SBIAS_OFF);
    const float** sAp   = (const float**)(smem + SAP_OFF);
    const float** sBp   = (const float**)(smem + SBP_OFF);
    int*          sRow  = (int*)(smem + SROW_OFF);
    float2*       sRed  = (float2*)(smem + SRED_OFF);

    if (tid < 128) {
        // rows
        int gr = rowTile * BM + tid;
        int orig = -1;
        if (gr < count) orig = (SEG == 0) ? gr : rlist[gr];
        sRow[tid] = orig;
        sAp[tid] = (orig >= 0) ? (input + (size_t)orig * DIM) : nullptr;
        // cols
        int sc = colTile * BN + tid;
        const float* bp = nullptr; float bv = -INFINITY;
        if (SEG == 0) {
            if (sc < SHORT)      { bp = weight + (size_t)sc * DIM;           bv = bias[sc]; }
            else if (sc < HEADC) { bp = tailv + (size_t)(sc - SHORT) * DIM;  bv = tailb[sc - SHORT]; }
        } else if (SEG == 1) {
            if (sc < SEG1C)      { bp = weight + (size_t)(SHORT + sc) * DIM; bv = bias[SHORT + sc]; }
        } else {
            if (sc < SEG2C)      { bp = weight + (size_t)(CUT1 + sc) * DIM;  bv = bias[CUT1 + sc]; }
        }
        sBp[tid] = bp; sBias[tid] = bv;
    }
    __syncthreads();

    // stage loader: 128 rows x 16 floats for A and B, 16B cp.async each
    auto load_stage = [&](int stage, int k0) {
        uint32_t a_s = sb + stage * STAGE_BYTES;
        uint32_t b_s = a_s + TILE_BYTES;
#pragma unroll
        for (int j = 0; j < 2; j++) {
            int li = tid + j * 256;
            int row = li >> 2, c4 = li & 3;
            const float* p = sAp[row];
            cp_async16(a_s + row * (ROWSTRIDE * 4) + c4 * 16,
                       p ? (const void*)(p + k0 + c4 * 4) : (const void*)input, p ? 16u : 0u);
        }
#pragma unroll
        for (int j = 0; j < 2; j++) {
            int li = tid + j * 256;
            int row = li >> 2, c4 = li & 3;
            const float* p = sBp[row];
            cp_async16(b_s + row * (ROWSTRIDE * 4) + c4 * 16,
                       p ? (const void*)(p + k0 + c4 * 4) : (const void*)input, p ? 16u : 0u);
        }
        cp_commit();
    };

    float acc[2][8][4];
#pragma unroll
    for (int i = 0; i < 2; i++)
#pragma unroll
        for (int j = 0; j < 8; j++)
#pragma unroll
            for (int q = 0; q < 4; q++) acc[i][j][q] = 0.f;

    load_stage(0, 0);
    load_stage(1, BK);

    for (int c = 0; c < NCHUNK; c++) {
        const int stage = c % NSTAGE;
        cp_wait1();
        __syncthreads();

        const float* As = (const float*)(smem + stage * STAGE_BYTES);
        const float* Bs = As + 128 * ROWSTRIDE;

#pragma unroll
        for (int k8 = 0; k8 < 2; k8++) {
            const int kk = k8 * 8 + t;
            uint32_t a[2][4];
#pragma unroll
            for (int i = 0; i < 2; i++) {
                const float* ap = As + (warpM * 32 + i * 16 + g) * ROWSTRIDE + kk;
                a[i][0] = __float_as_uint(ap[0]);
                a[i][1] = __float_as_uint(ap[8 * ROWSTRIDE]);
                a[i][2] = __float_as_uint(ap[4]);
                a[i][3] = __float_as_uint(ap[8 * ROWSTRIDE + 4]);
            }
#pragma unroll
            for (int j = 0; j < 8; j++) {
                const float* bp = Bs + (warpN * 64 + j * 8 + g) * ROWSTRIDE + kk;
                uint32_t b0 = __float_as_uint(bp[0]);
                uint32_t b1 = __float_as_uint(bp[4]);
                mma_tf32(acc[0][j], a[0], b0, b1);
                mma_tf32(acc[1][j], a[1], b0, b1);
            }
        }
        __syncthreads();

        int nc = c + (NSTAGE - 1);
        if (nc < NCHUNK) load_stage(nc % NSTAGE, nc * BK);
    }
    cp_wait0();

    // ---- epilogue: per-row (max, sumexp) over this 128-col tile ----
#pragma unroll
    for (int i = 0; i < 2; i++) {
#pragma unroll
        for (int h = 0; h < 2; h++) {
            int rlocal = warpM * 32 + i * 16 + h * 8 + g;
            float v[16];
            float m = -INFINITY;
#pragma unroll
            for (int j = 0; j < 8; j++) {
                float b0 = sBias[warpN * 64 + j * 8 + t * 2];
                float b1 = sBias[warpN * 64 + j * 8 + t * 2 + 1];
                float v0 = acc[i][j][h ? 2 : 0] + b0;
                float v1 = acc[i][j][h ? 3 : 1] + b1;
                v[j * 2]     = v0;
                v[j * 2 + 1] = v1;
                m = fmaxf(m, fmaxf(v0, v1));
            }
            float s = 0.f;
            if (m != -INFINITY) {
#pragma unroll
                for (int q = 0; q < 16; q++) s += expf(v[q] - m);
            }
            // quad reduce (lanes g*4 .. g*4+3)
#pragma unroll
            for (int off = 1; off <= 2; off <<= 1) {
                float m2 = __shfl_xor_sync(0xffffffffu, m, off);
                float s2 = __shfl_xor_sync(0xffffffffu, s, off);
                lse_merge(m, s, m2, s2);
            }
            if (t == 0) sRed[rlocal * 2 + warpN] = make_float2(m, s);
        }
    }
    __syncthreads();

    if (tid < 128) {
        float2 p0 = sRed[tid * 2];
        float2 p1 = sRed[tid * 2 + 1];
        float m = p0.x, s = p0.y;
        lse_merge(m, s, p1.x, p1.y);
        int orig = sRow[tid];
        if (orig >= 0)
            part[(size_t)orig * tiles + colTile] = make_float2(m, s);
    }
}

// ---------------- combine ----------------
__global__ void combine_kernel(const float* __restrict__ input,
                               const int*   __restrict__ target,
                               const float* __restrict__ weight,
                               const float* __restrict__ bias,
                               const float* __restrict__ tailv,
                               const float* __restrict__ tailb,
                               float* __restrict__ out)
{
    int gw   = (blockIdx.x * blockDim.x + threadIdx.x) >> 5;
    int lane = threadIdx.x & 31;
    if (gw >= N_ROWS) return;
    const int r = gw;

    const int t = target[r];
    const int cid = (t < SHORT) ? 0 : ((t < CUT1) ? 1 : 2);

    float m = -INFINITY, s = 0.f;
    for (int i = lane; i < HT; i += 32) {
        float2 q = g_headPart[(size_t)r * HT + i];
        lse_merge(m, s, q.x, q.y);
    }
#pragma unroll
    for (int off = 16; off; off >>= 1) {
        float m2 = __shfl_xor_sync(0xffffffffu, m, off);
        float s2 = __shfl_xor_sync(0xffffffffu, s, off);
        lse_merge(m, s, m2, s2);
    }
    float lseH = m + logf(s);

    const float* v; float bb;
    if (cid == 0) { v = weight + (size_t)t * DIM;        bb = bias[t]; }
    else          { v = tailv + (size_t)(cid - 1) * DIM; bb = tailb[cid - 1]; }
    const float4* xr = (const float4*)(input + (size_t)r * DIM);
    const float4* vv = (const float4*)v;
    float d = 0.f;
#pragma unroll
    for (int i = lane; i < DIM / 4; i += 32) {
        float4 a = xr[i], b = vv[i];
        d += a.x * b.x + a.y * b.y + a.z * b.z + a.w * b.w;
    }
#pragma unroll
    for (int off = 16; off; off >>= 1)
        d += __shfl_xor_sync(0xffffffffu, d, off);
    float res = (d + bb) - lseH;

    if (cid > 0) {
        const float4* wv = (const float4*)(weight + (size_t)t * DIM);
        float d2 = 0.f;
#pragma unroll
        for (int i = lane; i < DIM / 4; i += 32) {
            float4 a = xr[i], b = wv[i];
            d2 += a.x * b.x + a.y * b.y + a.z * b.z + a.w * b.w;
        }
#pragma unroll
        for (int off = 16; off; off >>= 1)
            d2 += __shfl_xor_sync(0xffffffffu, d2, off);
        float tl = d2 + bias[t];

        const float2* pt = (cid == 1) ? (g_seg1Part + (size_t)r * S1T)
                                      : (g_seg2Part + (size_t)r * S2T);
        const int T = (cid == 1) ? S1T : S2T;
        float mm = -INFINITY, ss = 0.f;
        for (int i = lane; i < T; i += 32) {
            float2 q = pt[i];
            lse_merge(mm, ss, q.x, q.y);
        }
#pragma unroll
        for (int off = 16; off; off >>= 1) {
            float m2 = __shfl_xor_sync(0xffffffffu, mm, off);
            float s2 = __shfl_xor_sync(0xffffffffu, ss, off);
            lse_merge(mm, ss, m2, s2);
        }
        res += tl - (mm + logf(ss));
    }

    if (lane == 0) out[r] = res;
}

// ---------------- loss ----------------
__global__ void loss_kernel(const float* __restrict__ out_vals,
                            float* __restrict__ loss_out)
{
    __shared__ float red[1024];
    int tid = threadIdx.x;
    float s = 0.f;
    for (int i = tid; i < N_ROWS; i += 1024) s += out_vals[i];
    red[tid] = s;
    __syncthreads();
    for (int stride = 512; stride > 0; stride >>= 1) {
        if (tid < stride) red[tid] += red[tid + stride];
        __syncthreads();
    }
    if (tid == 0) *loss_out = -red[0] / (float)N_ROWS;
}

// ---------------- launch ----------------
extern "C" void kernel_launch(void* const* d_in, const int* in_sizes, int n_in,
                              void* d_out, int out_size)
{
    const float* input  = (const float*)d_in[0];
    const int*   target = (const int*)  d_in[1];
    const float* weight = (const float*)d_in[2];
    const float* bias   = (const float*)d_in[3];
    const float* tailv  = (const float*)d_in[4];
    const float* tailb  = (const float*)d_in[5];
    float* out = (float*)d_out;

    cudaFuncSetAttribute(gemm_lse_tc<0>, cudaFuncAttributeMaxDynamicSharedMemorySize, SMEM_TOTAL);
    cudaFuncSetAttribute(gemm_lse_tc<1>, cudaFuncAttributeMaxDynamicSharedMemorySize, SMEM_TOTAL);
    cudaFuncSetAttribute(gemm_lse_tc<2>, cudaFuncAttributeMaxDynamicSharedMemorySize, SMEM_TOTAL);

    reset_kernel<<<1, 1>>>();
    classify_kernel<<<N_ROWS / 256, 256>>>(target);

    gemm_lse_tc<0><<<dim3(64, HT),  256, SMEM_TOTAL>>>(input, weight, bias, tailv, tailb);
    gemm_lse_tc<1><<<dim3(64, S1T), 256, SMEM_TOTAL>>>(input, weight, bias, tailv, tailb);
    gemm_lse_tc<2><<<dim3(64, S2T), 256, SMEM_TOTAL>>>(input, weight, bias, tailv, tailb);

    combine_kernel<<<(N_ROWS * 32) / 256, 256>>>(input, target, weight, bias,
                                                 tailv, tailb, out);

    if (out_size > N_ROWS)
        loss_kernel<<<1, 1024>>>(out, out + N_ROWS);
}

// round 6
// speedup vs baseline: 4.0806x; 1.0405x over previous
#include <cuda_runtime.h>
#include <math.h>
#include <stdint.h>

// ---------------- problem constants ----------------
#define N_ROWS   8192
#define DIM      1024
#define SHORT    4000
#define CUT1     20000
#define HEADC    4002
#define SEG1C    16000
#define SEG2C    30257

// ---------------- GEMM tiling ----------------
#define BM 128
#define BN 128
#define BK 16
#define NSTAGE 4
#define NCHUNK (DIM / BK)      // 64

#define HT   32                // ceil(4002/128)
#define S1T  125
#define S2T  237               // ceil(30257/128)

// smem layout: padded rows (16 data + 4 pad floats) -> conflict-free LDS
#define ROWSTRIDE 20
#define TILE_BYTES (128 * ROWSTRIDE * 4)     // 10240
#define STAGE_BYTES (2 * TILE_BYTES)         // 20480 (A then B)
#define META_OFF (NSTAGE * STAGE_BYTES)      // 81920
#define SBIAS_OFF (META_OFF)                 // 512 B
#define SAP_OFF   (META_OFF + 512)           // 1024 B
#define SBP_OFF   (META_OFF + 1536)          // 1024 B
#define SROW_OFF  (META_OFF + 2560)          // 512 B
#define SRED_OFF  (META_OFF + 3072)          // 2048 B (256 float2)
#define SMEM_TOTAL (META_OFF + 5120)         // 87040

// ---------------- scratch ----------------
__device__ float2 g_headPart[(size_t)N_ROWS * HT];
__device__ float2 g_seg1Part[(size_t)N_ROWS * S1T];
__device__ float2 g_seg2Part[(size_t)N_ROWS * S2T];
__device__ int    g_list1[N_ROWS];
__device__ int    g_list2[N_ROWS];
__device__ int    g_cnt[2];

// ---------------- helpers ----------------
__device__ __forceinline__ uint32_t smem_u32(const void* p) {
    uint32_t a;
    asm("{ .reg .u64 t; cvta.to.shared.u64 t, %1; cvt.u32.u64 %0, t; }" : "=r"(a) : "l"(p));
    return a;
}
__device__ __forceinline__ void cp_async16(uint32_t dst, const void* src, uint32_t szbytes) {
    asm volatile("cp.async.cg.shared.global [%0], [%1], 16, %2;\n"
                 :: "r"(dst), "l"(src), "r"(szbytes));
}
__device__ __forceinline__ void cp_commit() { asm volatile("cp.async.commit_group;"); }
__device__ __forceinline__ void cp_wait2()  { asm volatile("cp.async.wait_group 2;"); }

__device__ __forceinline__ void mma_tf32(float* d, const uint32_t* a, uint32_t b0, uint32_t b1) {
    asm volatile(
        "mma.sync.aligned.m16n8k8.row.col.f32.tf32.tf32.f32 "
        "{%0,%1,%2,%3}, {%4,%5,%6,%7}, {%8,%9}, {%0,%1,%2,%3};\n"
        : "+f"(d[0]), "+f"(d[1]), "+f"(d[2]), "+f"(d[3])
        : "r"(a[0]), "r"(a[1]), "r"(a[2]), "r"(a[3]), "r"(b0), "r"(b1));
}

__device__ __forceinline__ void lse_merge(float& m, float& s, float m2, float s2) {
    float M = fmaxf(m, m2);
    if (M == -INFINITY) { m = M; s = 0.f; return; }
    s = s * expf(m - M) + s2 * expf(m2 - M);
    m = M;
}

// ---------------- small kernels ----------------
__global__ void reset_kernel() { g_cnt[0] = 0; g_cnt[1] = 0; }

__global__ void classify_kernel(const int* __restrict__ target) {
    int r = blockIdx.x * blockDim.x + threadIdx.x;
    if (r >= N_ROWS) return;
    int t = target[r];
    if (t >= SHORT) {
        if (t < CUT1) g_list1[atomicAdd(&g_cnt[0], 1)] = r;
        else          g_list2[atomicAdd(&g_cnt[1], 1)] = r;
    }
}

// ---------------- tensor-core (mma.sync tf32) GEMM + LSE partials ----------------
template <int SEG>
__global__ __launch_bounds__(256, 2)
void gemm_lse_tc(const float* __restrict__ input,
                 const float* __restrict__ weight,
                 const float* __restrict__ bias,
                 const float* __restrict__ tailv,
                 const float* __restrict__ tailb)
{
    const int rowTile = blockIdx.x;
    const int colTile = blockIdx.y;

    int count; const int* rlist; float2* part; int tiles;
    if (SEG == 0)      { count = N_ROWS;   rlist = nullptr; part = g_headPart; tiles = HT;  }
    else if (SEG == 1) { count = g_cnt[0]; rlist = g_list1; part = g_seg1Part; tiles = S1T; }
    else               { count = g_cnt[1]; rlist = g_list2; part = g_seg2Part; tiles = S2T; }
    if (rowTile * BM >= count) return;

    extern __shared__ char smem[];
    const uint32_t sb = smem_u32(smem);
    const int tid  = threadIdx.x;
    const int lane = tid & 31;
    const int wid  = tid >> 5;
    const int warpM = wid >> 1;          // 0..3 -> 32-row band
    const int warpN = wid & 1;           // 0..1 -> 64-col half
    const int g = lane >> 2;             // group id 0..7
    const int t = lane & 3;              // thread-in-group

    float*        sBias = (float*)(smem + SBIAS_OFF);
    const float** sAp   = (const float**)(smem + SAP_OFF);
    const float** sBp   = (const float**)(smem + SBP_OFF);
    int*          sRow  = (int*)(smem + SROW_OFF);
    float2*       sRed  = (float2*)(smem + SRED_OFF);

    if (tid < 128) {
        // rows
        int gr = rowTile * BM + tid;
        int orig = -1;
        if (gr < count) orig = (SEG == 0) ? gr : rlist[gr];
        sRow[tid] = orig;
        sAp[tid] = (orig >= 0) ? (input + (size_t)orig * DIM) : nullptr;
        // cols
        int sc = colTile * BN + tid;
        const float* bp = nullptr; float bv = -INFINITY;
        if (SEG == 0) {
            if (sc < SHORT)      { bp = weight + (size_t)sc * DIM;           bv = bias[sc]; }
            else if (sc < HEADC) { bp = tailv + (size_t)(sc - SHORT) * DIM;  bv = tailb[sc - SHORT]; }
        } else if (SEG == 1) {
            if (sc < SEG1C)      { bp = weight + (size_t)(SHORT + sc) * DIM; bv = bias[SHORT + sc]; }
        } else {
            if (sc < SEG2C)      { bp = weight + (size_t)(CUT1 + sc) * DIM;  bv = bias[CUT1 + sc]; }
        }
        sBp[tid] = bp; sBias[tid] = bv;
    }
    __syncthreads();

    // ---- hoisted per-thread load metadata (loop-invariant) ----
    const int lrow = tid >> 2;          // 0..63
    const int c4   = tid & 3;           // 16B chunk id
    const float* pA0 = sAp[lrow];
    const float* pA1 = sAp[lrow + 64];
    const float* pB0 = sBp[lrow];
    const float* pB1 = sBp[lrow + 64];
    const uint32_t dA0 = lrow * (ROWSTRIDE * 4) + c4 * 16;
    const uint32_t dA1 = dA0 + 64 * (ROWSTRIDE * 4);
    const uint32_t szA0 = pA0 ? 16u : 0u, szA1 = pA1 ? 16u : 0u;
    const uint32_t szB0 = pB0 ? 16u : 0u, szB1 = pB1 ? 16u : 0u;
    const float* fA0 = pA0 ? pA0 + c4 * 4 : (const float*)input;
    const float* fA1 = pA1 ? pA1 + c4 * 4 : (const float*)input;
    const float* fB0 = pB0 ? pB0 + c4 * 4 : (const float*)input;
    const float* fB1 = pB1 ? pB1 + c4 * 4 : (const float*)input;

    auto load_stage = [&](uint32_t stbase, int k0) {
        cp_async16(stbase + dA0, fA0 + k0, szA0);
        cp_async16(stbase + dA1, fA1 + k0, szA1);
        cp_async16(stbase + TILE_BYTES + dA0, fB0 + k0, szB0);
        cp_async16(stbase + TILE_BYTES + dA1, fB1 + k0, szB1);
        cp_commit();
    };

    float acc[2][8][4];
#pragma unroll
    for (int i = 0; i < 2; i++)
#pragma unroll
        for (int j = 0; j < 8; j++)
#pragma unroll
            for (int q = 0; q < 4; q++) acc[i][j][q] = 0.f;

    load_stage(sb, 0);
    load_stage(sb + STAGE_BYTES, BK);
    load_stage(sb + 2 * STAGE_BYTES, 2 * BK);

    // per-warp fragment bases (floats) within a stage
    const int aFBase = (warpM * 32 + g) * ROWSTRIDE + t;
    const int bFBase = (warpN * 64 + g) * ROWSTRIDE + t;

#pragma unroll 1
    for (int cb = 0; cb < NCHUNK; cb += 4) {
#pragma unroll
        for (int u = 0; u < 4; u++) {
            const int c = cb + u;
            cp_wait2();
            __syncthreads();

            const float* As = (const float*)(smem + u * STAGE_BYTES) + aFBase;
            const float* Bs = (const float*)(smem + u * STAGE_BYTES + TILE_BYTES) + bFBase;

#pragma unroll
            for (int k8 = 0; k8 < 2; k8++) {
                const int kk = k8 * 8;
                uint32_t a[2][4];
#pragma unroll
                for (int i = 0; i < 2; i++) {
                    const float* ap = As + i * 16 * ROWSTRIDE + kk;
                    a[i][0] = __float_as_uint(ap[0]);
                    a[i][1] = __float_as_uint(ap[8 * ROWSTRIDE]);
                    a[i][2] = __float_as_uint(ap[4]);
                    a[i][3] = __float_as_uint(ap[8 * ROWSTRIDE + 4]);
                }
                uint32_t b[8][2];
#pragma unroll
                for (int j = 0; j < 8; j++) {
                    const float* bp = Bs + j * 8 * ROWSTRIDE + kk;
                    b[j][0] = __float_as_uint(bp[0]);
                    b[j][1] = __float_as_uint(bp[4]);
                }
#pragma unroll
                for (int j = 0; j < 8; j++) {
                    mma_tf32(acc[0][j], a[0], b[j][0], b[j][1]);
                    mma_tf32(acc[1][j], a[1], b[j][0], b[j][1]);
                }
            }

            if (c + 3 < NCHUNK) {
                const int ns = (u + 3) & 3;
                load_stage(sb + ns * STAGE_BYTES, (c + 3) * BK);
            }
        }
    }

    // ---- epilogue: per-row (max, sumexp) over this 128-col tile ----
#pragma unroll
    for (int i = 0; i < 2; i++) {
#pragma unroll
        for (int h = 0; h < 2; h++) {
            int rlocal = warpM * 32 + i * 16 + h * 8 + g;
            float v[16];
            float m = -INFINITY;
#pragma unroll
            for (int j = 0; j < 8; j++) {
                float b0 = sBias[warpN * 64 + j * 8 + t * 2];
                float b1 = sBias[warpN * 64 + j * 8 + t * 2 + 1];
                float v0 = acc[i][j][h ? 2 : 0] + b0;
                float v1 = acc[i][j][h ? 3 : 1] + b1;
                v[j * 2]     = v0;
                v[j * 2 + 1] = v1;
                m = fmaxf(m, fmaxf(v0, v1));
            }
            float s = 0.f;
            if (m != -INFINITY) {
#pragma unroll
                for (int q = 0; q < 16; q++) s += expf(v[q] - m);
            }
            // quad reduce (lanes g*4 .. g*4+3)
#pragma unroll
            for (int off = 1; off <= 2; off <<= 1) {
                float m2 = __shfl_xor_sync(0xffffffffu, m, off);
                float s2 = __shfl_xor_sync(0xffffffffu, s, off);
                lse_merge(m, s, m2, s2);
            }
            if (t == 0) sRed[rlocal * 2 + warpN] = make_float2(m, s);
        }
    }
    __syncthreads();

    if (tid < 128) {
        float2 p0 = sRed[tid * 2];
        float2 p1 = sRed[tid * 2 + 1];
        float m = p0.x, s = p0.y;
        lse_merge(m, s, p1.x, p1.y);
        int orig = sRow[tid];
        if (orig >= 0)
            part[(size_t)orig * tiles + colTile] = make_float2(m, s);
    }
}

// ---------------- combine ----------------
__global__ void combine_kernel(const float* __restrict__ input,
                               const int*   __restrict__ target,
                               const float* __restrict__ weight,
                               const float* __restrict__ bias,
                               const float* __restrict__ tailv,
                               const float* __restrict__ tailb,
                               float* __restrict__ out)
{
    int gw   = (blockIdx.x * blockDim.x + threadIdx.x) >> 5;
    int lane = threadIdx.x & 31;
    if (gw >= N_ROWS) return;
    const int r = gw;

    const int t = target[r];
    const int cid = (t < SHORT) ? 0 : ((t < CUT1) ? 1 : 2);

    float m = -INFINITY, s = 0.f;
    for (int i = lane; i < HT; i += 32) {
        float2 q = g_headPart[(size_t)r * HT + i];
        lse_merge(m, s, q.x, q.y);
    }
#pragma unroll
    for (int off = 16; off; off >>= 1) {
        float m2 = __shfl_xor_sync(0xffffffffu, m, off);
        float s2 = __shfl_xor_sync(0xffffffffu, s, off);
        lse_merge(m, s, m2, s2);
    }
    float lseH = m + logf(s);

    const float* v; float bb;
    if (cid == 0) { v = weight + (size_t)t * DIM;        bb = bias[t]; }
    else          { v = tailv + (size_t)(cid - 1) * DIM; bb = tailb[cid - 1]; }
    const float4* xr = (const float4*)(input + (size_t)r * DIM);
    const float4* vv = (const float4*)v;
    float d = 0.f;
#pragma unroll
    for (int i = lane; i < DIM / 4; i += 32) {
        float4 a = xr[i], b = vv[i];
        d += a.x * b.x + a.y * b.y + a.z * b.z + a.w * b.w;
    }
#pragma unroll
    for (int off = 16; off; off >>= 1)
        d += __shfl_xor_sync(0xffffffffu, d, off);
    float res = (d + bb) - lseH;

    if (cid > 0) {
        const float4* wv = (const float4*)(weight + (size_t)t * DIM);
        float d2 = 0.f;
#pragma unroll
        for (int i = lane; i < DIM / 4; i += 32) {
            float4 a = xr[i], b = wv[i];
            d2 += a.x * b.x + a.y * b.y + a.z * b.z + a.w * b.w;
        }
#pragma unroll
        for (int off = 16; off; off >>= 1)
            d2 += __shfl_xor_sync(0xffffffffu, d2, off);
        float tl = d2 + bias[t];

        const float2* pt = (cid == 1) ? (g_seg1Part + (size_t)r * S1T)
                                      : (g_seg2Part + (size_t)r * S2T);
        const int T = (cid == 1) ? S1T : S2T;
        float mm = -INFINITY, ss = 0.f;
        for (int i = lane; i < T; i += 32) {
            float2 q = pt[i];
            lse_merge(mm, ss, q.x, q.y);
        }
#pragma unroll
        for (int off = 16; off; off >>= 1) {
            float m2 = __shfl_xor_sync(0xffffffffu, mm, off);
            float s2 = __shfl_xor_sync(0xffffffffu, ss, off);
            lse_merge(mm, ss, m2, s2);
        }
        res += tl - (mm + logf(ss));
    }

    if (lane == 0) out[r] = res;
}

// ---------------- loss ----------------
__global__ void loss_kernel(const float* __restrict__ out_vals,
                            float* __restrict__ loss_out)
{
    __shared__ float red[1024];
    int tid = threadIdx.x;
    float s = 0.f;
    for (int i = tid; i < N_ROWS; i += 1024) s += out_vals[i];
    red[tid] = s;
    __syncthreads();
    for (int stride = 512; stride > 0; stride >>= 1) {
        if (tid < stride) red[tid] += red[tid + stride];
        __syncthreads();
    }
    if (tid == 0) *loss_out = -red[0] / (float)N_ROWS;
}

// ---------------- launch ----------------
extern "C" void kernel_launch(void* const* d_in, const int* in_sizes, int n_in,
                              void* d_out, int out_size)
{
    const float* input  = (const float*)d_in[0];
    const int*   target = (const int*)  d_in[1];
    const float* weight = (const float*)d_in[2];
    const float* bias   = (const float*)d_in[3];
    const float* tailv  = (const float*)d_in[4];
    const float* tailb  = (const float*)d_in[5];
    float* out = (float*)d_out;

    cudaFuncSetAttribute(gemm_lse_tc<0>, cudaFuncAttributeMaxDynamicSharedMemorySize, SMEM_TOTAL);
    cudaFuncSetAttribute(gemm_lse_tc<1>, cudaFuncAttributeMaxDynamicSharedMemorySize, SMEM_TOTAL);
    cudaFuncSetAttribute(gemm_lse_tc<2>, cudaFuncAttributeMaxDynamicSharedMemorySize, SMEM_TOTAL);

    reset_kernel<<<1, 1>>>();
    classify_kernel<<<N_ROWS / 256, 256>>>(target);

    gemm_lse_tc<0><<<dim3(64, HT),  256, SMEM_TOTAL>>>(input, weight, bias, tailv, tailb);
    gemm_lse_tc<1><<<dim3(64, S1T), 256, SMEM_TOTAL>>>(input, weight, bias, tailv, tailb);
    gemm_lse_tc<2><<<dim3(64, S2T), 256, SMEM_TOTAL>>>(input, weight, bias, tailv, tailb);

    combine_kernel<<<(N_ROWS * 32) / 256, 256>>>(input, target, weight, bias,
                                                 tailv, tailb, out);

    if (out_size > N_ROWS)
        loss_kernel<<<1, 1024>>>(out, out + N_ROWS);
}